// round 1
// baseline (speedup 1.0000x reference)
#include <cuda_runtime.h>
#include <math.h>

#define N_ROWS 3456      // 16 * 216
#define C_DIM  256
#define K_CODES 1024
#define B_SZ   16
#define SPAT   216       // 6*6*6
#define VOX    13824     // 24^3
#define OUT_ZQ (B_SZ * C_DIM * SPAT)   // 884736
#define OUT_LOSS OUT_ZQ                // index 884736
#define OUT_IDX (OUT_ZQ + 1)           // 884737

#define TS 64
#define KC 64
#define LDS_S 68   // padded smem row stride (floats)

// ---------------- device scratch (no allocation allowed) ----------------
__device__ float g_zn[N_ROWS * C_DIM];
__device__ float g_en[K_CODES * C_DIM];
__device__ float g_aff[N_ROWS * K_CODES];
__device__ unsigned long long g_pat[N_ROWS];
__device__ float g_avgp[K_CODES];
__device__ float g_sums[8];  // 0: SSE, 1: sum sample-entropy, 2: sumW, 3: sumWcos

// ---------------- helpers ----------------
__device__ __forceinline__ float bsum256(float v, float* red) {
    // block reduce sum, 256 threads (8 warps). red[] >= 8 floats.
    #pragma unroll
    for (int o = 16; o; o >>= 1) v += __shfl_xor_sync(0xffffffffu, v, o);
    __syncthreads();               // guard red reuse
    if ((threadIdx.x & 31) == 0) red[threadIdx.x >> 5] = v;
    __syncthreads();
    float s = 0.f;
    #pragma unroll
    for (int w = 0; w < 8; w++) s += red[w];
    return s;                      // identical in all threads
}

// ---------------- K0: zero accumulators ----------------
__global__ void k_zero() {
    int t = threadIdx.x;
    if (t < K_CODES) g_avgp[t] = 0.f;
    if (t < 8) g_sums[t] = 0.f;
}

// ---------------- K1: normalize z rows ----------------
__global__ void k_norm_z(const float* __restrict__ z_e) {
    int n = blockIdx.x, c = threadIdx.x;
    int b = n / SPAT, s = n % SPAT;
    __shared__ float red[8];
    float v = z_e[(b * C_DIM + c) * SPAT + s];
    float ss = bsum256(v * v, red);
    float nrm = sqrtf(ss);
    g_zn[n * C_DIM + c] = v / fmaxf(nrm, 1e-12f);
}

// ---------------- K2: normalize codebook rows ----------------
__global__ void k_norm_cb(const float* __restrict__ cb) {
    int k = blockIdx.x, c = threadIdx.x;
    __shared__ float red[8];
    float v = cb[k * C_DIM + c];
    float ss = bsum256(v * v, red);
    float nrm = sqrtf(ss);
    g_en[k * C_DIM + c] = v / fmaxf(nrm, 1e-12f);
}

// ---------------- K3: binary occupancy patterns ----------------
__global__ void k_pattern(const float* __restrict__ inp) {
    int v = blockIdx.x * 64 + threadIdx.x;   // voxel id
    int b = v / VOX, s = v % VOX;
    const float* p = inp + (size_t)b * 32 * VOX + s;
    float best = p[0];
    int bi = 0;
    #pragma unroll
    for (int c = 1; c < 32; c++) {
        float x = p[c * VOX];
        if (x > best) { best = x; bi = c; }   // first-occurrence argmax
    }
    unsigned m = __ballot_sync(0xffffffffu, bi != 0);
    __shared__ unsigned sm[2];
    if ((threadIdx.x & 31) == 0) sm[threadIdx.x >> 5] = m;
    __syncthreads();
    if (threadIdx.x == 0)
        g_pat[blockIdx.x] = (unsigned long long)sm[0] | ((unsigned long long)sm[1] << 32);
}

// ---------------- K4a: affinity = zn @ en^T  (fp32 tiled GEMM) ----------------
__global__ __launch_bounds__(256) void k_affinity() {
    __shared__ float As[KC * LDS_S];
    __shared__ float Bs[KC * LDS_S];
    int tid = threadIdx.x;
    int ty = tid >> 4, tx = tid & 15;          // 16x16 thread grid
    int rowBase = blockIdx.y * TS;
    int colBase = blockIdx.x * TS;
    const float* A = g_zn + rowBase * C_DIM;
    const float* B = g_en + colBase * C_DIM;
    int ln = tid >> 2;                 // 0..63 : tile row
    int lc = (tid & 3) * 16;           // 0,16,32,48 : c-group base
    float acc[4][4] = {};
    for (int kc = 0; kc < C_DIM; kc += KC) {
        __syncthreads();
        #pragma unroll
        for (int q = 0; q < 4; q++) {
            int cl = lc + q * 4;
            float4 a4 = *(const float4*)&A[ln * C_DIM + kc + cl];
            As[(cl + 0) * LDS_S + ln] = a4.x;
            As[(cl + 1) * LDS_S + ln] = a4.y;
            As[(cl + 2) * LDS_S + ln] = a4.z;
            As[(cl + 3) * LDS_S + ln] = a4.w;
            float4 b4 = *(const float4*)&B[ln * C_DIM + kc + cl];
            Bs[(cl + 0) * LDS_S + ln] = b4.x;
            Bs[(cl + 1) * LDS_S + ln] = b4.y;
            Bs[(cl + 2) * LDS_S + ln] = b4.z;
            Bs[(cl + 3) * LDS_S + ln] = b4.w;
        }
        __syncthreads();
        #pragma unroll 16
        for (int c = 0; c < KC; c++) {
            float4 a = *(const float4*)&As[c * LDS_S + ty * 4];
            float4 b = *(const float4*)&Bs[c * LDS_S + tx * 4];
            float av[4] = {a.x, a.y, a.z, a.w};
            float bv[4] = {b.x, b.y, b.z, b.w};
            #pragma unroll
            for (int i = 0; i < 4; i++)
                #pragma unroll
                for (int j = 0; j < 4; j++)
                    acc[i][j] += av[i] * bv[j];
        }
    }
    #pragma unroll
    for (int i = 0; i < 4; i++) {
        int n = rowBase + ty * 4 + i;
        float4 o = make_float4(acc[i][0], acc[i][1], acc[i][2], acc[i][3]);
        *(float4*)&g_aff[n * K_CODES + colBase + tx * 4] = o;
    }
}

// ---------------- K4b: per-row softmax/argmax/entropy/SSE/output ----------------
__global__ __launch_bounds__(256) void k_row(float* __restrict__ out) {
    int n = blockIdx.x, t = threadIdx.x;
    __shared__ float red[8];
    __shared__ float redm[8];
    __shared__ int   redi[8];

    float fa[4];
    #pragma unroll
    for (int q = 0; q < 4; q++)
        fa[q] = g_aff[n * K_CODES + t + q * 256] * 100.0f;  // / TEMP

    // thread-local argmax (ascending k order -> first-occurrence on ties)
    float m = fa[0]; int mi = t;
    #pragma unroll
    for (int q = 1; q < 4; q++)
        if (fa[q] > m) { m = fa[q]; mi = t + q * 256; }
    // warp argmax
    #pragma unroll
    for (int o = 16; o; o >>= 1) {
        float om = __shfl_xor_sync(0xffffffffu, m, o);
        int   oi = __shfl_xor_sync(0xffffffffu, mi, o);
        if (om > m || (om == m && oi < mi)) { m = om; mi = oi; }
    }
    if ((t & 31) == 0) { redm[t >> 5] = m; redi[t >> 5] = mi; }
    __syncthreads();
    float bm = redm[0]; int bidx = redi[0];
    #pragma unroll
    for (int w = 1; w < 8; w++)
        if (redm[w] > bm || (redm[w] == bm && redi[w] < bidx)) { bm = redm[w]; bidx = redi[w]; }

    // softmax sums
    float e[4], se = 0.f, te = 0.f;
    #pragma unroll
    for (int q = 0; q < 4; q++) {
        float d = fa[q] - bm;
        e[q] = expf(d);
        se += e[q];
        te += e[q] * d;
    }
    float Z = bsum256(se, red);
    float T = bsum256(te, red);
    float logZ = logf(Z);

    if (t == 0) {
        atomicAdd(&g_sums[1], logZ - T / Z);        // -sum p log p for this row
        out[OUT_IDX + n] = (float)bidx;             // idx output
    }
    // avg_probs accumulation
    float invZN = 1.0f / (Z * (float)N_ROWS);
    #pragma unroll
    for (int q = 0; q < 4; q++)
        atomicAdd(&g_avgp[t + q * 256], e[q] * invZN);

    // SSE and straight-through output (forward value == en[idx])
    float zq = g_en[bidx * C_DIM + t];
    float zn = g_zn[n * C_DIM + t];
    float d = zq - zn;
    float sse = bsum256(d * d, red);
    if (t == 0) atomicAdd(&g_sums[0], sse);
    int b = n / SPAT, s = n % SPAT;
    out[(b * C_DIM + t) * SPAT + s] = zq;
}

// ---------------- K5: fused cos GEMM + hamming mask + weighted reduce ----------------
__global__ __launch_bounds__(256) void k_ham() {
    int it = blockIdx.y, jt = blockIdx.x;
    if (jt < it) return;   // symmetry: upper triangle only
    __shared__ float As[KC * LDS_S];
    __shared__ float Bs[KC * LDS_S];
    __shared__ unsigned long long spi[64], spj[64];
    __shared__ float red[8];
    int tid = threadIdx.x;
    int ty = tid >> 4, tx = tid & 15;
    const float* A = g_zn + it * TS * C_DIM;
    const float* B = g_zn + jt * TS * C_DIM;
    if (tid < 64)       spi[tid] = g_pat[it * 64 + tid];
    else if (tid < 128) spj[tid - 64] = g_pat[jt * 64 + tid - 64];
    int ln = tid >> 2;
    int lc = (tid & 3) * 16;
    float acc[4][4] = {};
    for (int kc = 0; kc < C_DIM; kc += KC) {
        __syncthreads();
        #pragma unroll
        for (int q = 0; q < 4; q++) {
            int cl = lc + q * 4;
            float4 a4 = *(const float4*)&A[ln * C_DIM + kc + cl];
            As[(cl + 0) * LDS_S + ln] = a4.x;
            As[(cl + 1) * LDS_S + ln] = a4.y;
            As[(cl + 2) * LDS_S + ln] = a4.z;
            As[(cl + 3) * LDS_S + ln] = a4.w;
            float4 b4 = *(const float4*)&B[ln * C_DIM + kc + cl];
            Bs[(cl + 0) * LDS_S + ln] = b4.x;
            Bs[(cl + 1) * LDS_S + ln] = b4.y;
            Bs[(cl + 2) * LDS_S + ln] = b4.z;
            Bs[(cl + 3) * LDS_S + ln] = b4.w;
        }
        __syncthreads();
        #pragma unroll 16
        for (int c = 0; c < KC; c++) {
            float4 a = *(const float4*)&As[c * LDS_S + ty * 4];
            float4 b = *(const float4*)&Bs[c * LDS_S + tx * 4];
            float av[4] = {a.x, a.y, a.z, a.w};
            float bv[4] = {b.x, b.y, b.z, b.w};
            #pragma unroll
            for (int i = 0; i < 4; i++)
                #pragma unroll
                for (int j = 0; j < 4; j++)
                    acc[i][j] += av[i] * bv[j];
        }
    }
    // epilogue: hamming weight + reduce (cos == acc since rows are unit-norm)
    float ws = 0.f, wc = 0.f;
    #pragma unroll
    for (int i = 0; i < 4; i++) {
        int li = ty * 4 + i;
        int gi = it * 64 + li;
        unsigned long long pi = spi[li];
        #pragma unroll
        for (int j = 0; j < 4; j++) {
            int lj = tx * 4 + j;
            int gj = jt * 64 + lj;
            int h = __popcll(pi ^ spj[lj]);
            if (gi != gj && h <= 5) {           // sim > 0.92
                float w = 1.0f - (float)h * (1.0f / 64.0f);
                ws += w;
                wc += w * acc[i][j];
            }
        }
    }
    float scale = (it == jt) ? 1.0f : 2.0f;
    float wsb = bsum256(ws * scale, red);
    float wcb = bsum256(wc * scale, red);
    if (tid == 0) {
        atomicAdd(&g_sums[2], wsb);
        atomicAdd(&g_sums[3], wcb);
    }
}

// ---------------- K6: final scalar combine ----------------
__global__ __launch_bounds__(256) void k_final(float* __restrict__ out) {
    __shared__ float red[8];
    int t = threadIdx.x;
    float v = 0.f;
    #pragma unroll
    for (int q = 0; q < 4; q++) {
        float p = g_avgp[t + q * 256];
        v += p * logf(p + 1e-5f);
    }
    float s = bsum256(v, red);          // = sum p log(p+1e-5)
    if (t == 0) {
        float sse  = g_sums[0];
        float sent = g_sums[1];
        float sw   = g_sums[2];
        float swc  = g_sums[3];
        float codebook_loss = sse / (float)(N_ROWS * C_DIM);
        float commit_loss   = 0.25f * codebook_loss;
        float sample_entropy = sent / (float)N_ROWS;
        float avg_entropy    = -s;
        float ent_loss = 0.1f * (sample_entropy - avg_entropy);
        float ham_loss = (sw - swc) / (sw + 1e-8f);
        out[OUT_LOSS] = codebook_loss + commit_loss + ent_loss + ham_loss;
    }
}

// ---------------- launch ----------------
extern "C" void kernel_launch(void* const* d_in, const int* in_sizes, int n_in,
                              void* d_out, int out_size) {
    const float* input_blocks = (const float*)d_in[0];
    const float* z_e          = (const float*)d_in[1];
    const float* codebook     = (const float*)d_in[2];
    float* out = (float*)d_out;

    k_zero<<<1, 1024>>>();
    k_norm_z<<<N_ROWS, 256>>>(z_e);
    k_norm_cb<<<K_CODES, 256>>>(codebook);
    k_pattern<<<N_ROWS, 64>>>(input_blocks);
    k_affinity<<<dim3(K_CODES / TS, N_ROWS / TS), 256>>>();
    k_row<<<N_ROWS, 256>>>(out);
    k_ham<<<dim3(N_ROWS / TS, N_ROWS / TS), 256>>>();
    k_final<<<1, 256>>>(out);
}

// round 3
// speedup vs baseline: 1.6362x; 1.6362x over previous
#include <cuda_runtime.h>
#include <cuda_bf16.h>
#include <math.h>
#include <stdint.h>

#define N_ROWS 3456      // 16 * 216
#define C_DIM  256
#define K_CODES 1024
#define B_SZ   16
#define SPAT   216       // 6*6*6
#define VOX    13824     // 24^3
#define OUT_ZQ (B_SZ * C_DIM * SPAT)   // 884736
#define OUT_LOSS OUT_ZQ
#define OUT_IDX (OUT_ZQ + 1)

#define TS 64
#define KC 64
#define LDS_S 68   // padded fp32 smem stride

// ---------------- device scratch ----------------
__device__ float g_zn[N_ROWS * C_DIM];          // fp32 normalized z
__device__ __nv_bfloat16 g_znh[N_ROWS * C_DIM]; // bf16 copy (cos GEMM)
__device__ float g_en[K_CODES * C_DIM];         // fp32 normalized codebook
__device__ float g_aff[N_ROWS * K_CODES];
__device__ unsigned long long g_pat[N_ROWS];
__device__ float g_avgp[K_CODES];
__device__ float g_sums[8];  // 0: SSE, 1: sample-entropy sum, 2: sumW, 3: sumWcos

// ---------------- helpers ----------------
__device__ __forceinline__ float bsum256(float v, float* red) {
    #pragma unroll
    for (int o = 16; o; o >>= 1) v += __shfl_xor_sync(0xffffffffu, v, o);
    __syncthreads();
    if ((threadIdx.x & 31) == 0) red[threadIdx.x >> 5] = v;
    __syncthreads();
    float s = 0.f;
    #pragma unroll
    for (int w = 0; w < 8; w++) s += red[w];
    return s;
}

__device__ __forceinline__ void ldsm_x4(uint32_t& r0, uint32_t& r1, uint32_t& r2, uint32_t& r3, uint32_t addr) {
    asm volatile("ldmatrix.sync.aligned.m8n8.x4.shared.b16 {%0,%1,%2,%3}, [%4];"
                 : "=r"(r0), "=r"(r1), "=r"(r2), "=r"(r3) : "r"(addr));
}
__device__ __forceinline__ void ldsm_x2(uint32_t& r0, uint32_t& r1, uint32_t addr) {
    asm volatile("ldmatrix.sync.aligned.m8n8.x2.shared.b16 {%0,%1}, [%2];"
                 : "=r"(r0), "=r"(r1) : "r"(addr));
}
__device__ __forceinline__ void mma_bf16(float* c, uint32_t a0, uint32_t a1, uint32_t a2, uint32_t a3,
                                         uint32_t b0, uint32_t b1) {
    asm volatile("mma.sync.aligned.m16n8k16.row.col.f32.bf16.bf16.f32 "
                 "{%0,%1,%2,%3}, {%4,%5,%6,%7}, {%8,%9}, {%0,%1,%2,%3};"
                 : "+f"(c[0]), "+f"(c[1]), "+f"(c[2]), "+f"(c[3])
                 : "r"(a0), "r"(a1), "r"(a2), "r"(a3), "r"(b0), "r"(b1));
}

// ---------------- K0: zero accumulators ----------------
__global__ void k_zero() {
    int t = threadIdx.x;
    if (t < K_CODES) g_avgp[t] = 0.f;
    if (t < 8) g_sums[t] = 0.f;
}

// ---------------- K1: normalize z rows (+ bf16 copy) ----------------
__global__ void k_norm_z(const float* __restrict__ z_e) {
    int n = blockIdx.x, c = threadIdx.x;
    int b = n / SPAT, s = n % SPAT;
    __shared__ float red[8];
    float v = z_e[(b * C_DIM + c) * SPAT + s];
    float ss = bsum256(v * v, red);
    float nrm = sqrtf(ss);
    float vn = v / fmaxf(nrm, 1e-12f);
    g_zn[n * C_DIM + c] = vn;
    g_znh[n * C_DIM + c] = __float2bfloat16_rn(vn);
}

// ---------------- K2: normalize codebook rows ----------------
__global__ void k_norm_cb(const float* __restrict__ cb) {
    int k = blockIdx.x, c = threadIdx.x;
    __shared__ float red[8];
    float v = cb[k * C_DIM + c];
    float ss = bsum256(v * v, red);
    float nrm = sqrtf(ss);
    g_en[k * C_DIM + c] = v / fmaxf(nrm, 1e-12f);
}

// ---------------- K3: binary occupancy patterns (4 patterns/block) ----------------
__global__ __launch_bounds__(256) void k_pattern(const float* __restrict__ inp) {
    int t = threadIdx.x;
    int p_in_blk = t >> 6;
    int gp = blockIdx.x * 4 + p_in_blk;
    int t64 = t & 63;
    int v = gp * 64 + t64;
    int b = v / VOX, s = v % VOX;
    const float* p = inp + (size_t)b * 32 * VOX + s;
    float best = __ldg(&p[0]);
    int bi = 0;
    #pragma unroll
    for (int c = 1; c < 32; c++) {
        float x = __ldg(&p[c * VOX]);
        if (x > best) { best = x; bi = c; }
    }
    unsigned m = __ballot_sync(0xffffffffu, bi != 0);
    __shared__ unsigned sm[8];
    if ((t & 31) == 0) sm[t >> 5] = m;
    __syncthreads();
    if (t64 == 0)
        g_pat[gp] = (unsigned long long)sm[2 * p_in_blk] |
                    ((unsigned long long)sm[2 * p_in_blk + 1] << 32);
}

// ---------------- K4a: affinity = zn @ en^T (fp32 FFMA tiled GEMM, exact) ----------------
__global__ __launch_bounds__(256) void k_affinity() {
    __shared__ float As[KC * LDS_S];
    __shared__ float Bs[KC * LDS_S];
    int tid = threadIdx.x;
    int ty = tid >> 4, tx = tid & 15;
    int rowBase = blockIdx.y * TS;
    int colBase = blockIdx.x * TS;
    const float* A = g_zn + rowBase * C_DIM;
    const float* B = g_en + colBase * C_DIM;
    int ln = tid >> 2;
    int lc = (tid & 3) * 16;
    float acc[4][4] = {};
    for (int kc = 0; kc < C_DIM; kc += KC) {
        __syncthreads();
        #pragma unroll
        for (int q = 0; q < 4; q++) {
            int cl = lc + q * 4;
            float4 a4 = *(const float4*)&A[ln * C_DIM + kc + cl];
            As[(cl + 0) * LDS_S + ln] = a4.x;
            As[(cl + 1) * LDS_S + ln] = a4.y;
            As[(cl + 2) * LDS_S + ln] = a4.z;
            As[(cl + 3) * LDS_S + ln] = a4.w;
            float4 b4 = *(const float4*)&B[ln * C_DIM + kc + cl];
            Bs[(cl + 0) * LDS_S + ln] = b4.x;
            Bs[(cl + 1) * LDS_S + ln] = b4.y;
            Bs[(cl + 2) * LDS_S + ln] = b4.z;
            Bs[(cl + 3) * LDS_S + ln] = b4.w;
        }
        __syncthreads();
        #pragma unroll 16
        for (int c = 0; c < KC; c++) {
            float4 a = *(const float4*)&As[c * LDS_S + ty * 4];
            float4 b = *(const float4*)&Bs[c * LDS_S + tx * 4];
            float av[4] = {a.x, a.y, a.z, a.w};
            float bv[4] = {b.x, b.y, b.z, b.w};
            #pragma unroll
            for (int i = 0; i < 4; i++)
                #pragma unroll
                for (int j = 0; j < 4; j++)
                    acc[i][j] += av[i] * bv[j];
        }
    }
    #pragma unroll
    for (int i = 0; i < 4; i++) {
        int n = rowBase + ty * 4 + i;
        float4 o = make_float4(acc[i][0], acc[i][1], acc[i][2], acc[i][3]);
        *(float4*)&g_aff[n * K_CODES + colBase + tx * 4] = o;
    }
}

// ---------------- K4b: per-row softmax/argmax/entropy/SSE/output ----------------
__global__ __launch_bounds__(256) void k_row(float* __restrict__ out) {
    int n = blockIdx.x, t = threadIdx.x;
    __shared__ float red[8];
    __shared__ float redm[8];
    __shared__ int   redi[8];

    float fa[4];
    #pragma unroll
    for (int q = 0; q < 4; q++)
        fa[q] = g_aff[n * K_CODES + t + q * 256] * 100.0f;

    float m = fa[0]; int mi = t;
    #pragma unroll
    for (int q = 1; q < 4; q++)
        if (fa[q] > m) { m = fa[q]; mi = t + q * 256; }
    #pragma unroll
    for (int o = 16; o; o >>= 1) {
        float om = __shfl_xor_sync(0xffffffffu, m, o);
        int   oi = __shfl_xor_sync(0xffffffffu, mi, o);
        if (om > m || (om == m && oi < mi)) { m = om; mi = oi; }
    }
    if ((t & 31) == 0) { redm[t >> 5] = m; redi[t >> 5] = mi; }
    __syncthreads();
    float bm = redm[0]; int bidx = redi[0];
    #pragma unroll
    for (int w = 1; w < 8; w++)
        if (redm[w] > bm || (redm[w] == bm && redi[w] < bidx)) { bm = redm[w]; bidx = redi[w]; }

    float e[4], se = 0.f, te = 0.f;
    #pragma unroll
    for (int q = 0; q < 4; q++) {
        float d = fa[q] - bm;
        e[q] = expf(d);
        se += e[q];
        te += e[q] * d;
    }
    float Z = bsum256(se, red);
    float T = bsum256(te, red);
    float logZ = logf(Z);

    if (t == 0) {
        atomicAdd(&g_sums[1], logZ - T / Z);
        out[OUT_IDX + n] = (float)bidx;
    }
    float invZN = 1.0f / (Z * (float)N_ROWS);
    #pragma unroll
    for (int q = 0; q < 4; q++)
        atomicAdd(&g_avgp[t + q * 256], e[q] * invZN);

    float zq = g_en[bidx * C_DIM + t];
    float zn = g_zn[n * C_DIM + t];
    float d = zq - zn;
    float sse = bsum256(d * d, red);
    if (t == 0) atomicAdd(&g_sums[0], sse);
    int b = n / SPAT, s = n % SPAT;
    out[(b * C_DIM + t) * SPAT + s] = zq;
}

// ---------------- K5: fused cos GEMM (bf16 mma) + hamming reduce ----------------
#define HM_KC 128
#define HM_LDS 136  // bf16 stride; 272B row ≡ 16B mod 128B -> conflict-free ldmatrix
__global__ __launch_bounds__(256) void k_ham() {
    int it = blockIdx.y, jt = blockIdx.x;
    if (jt < it) return;
    __shared__ __nv_bfloat16 Ahs[64 * HM_LDS];
    __shared__ __nv_bfloat16 Bhs[64 * HM_LDS];
    __shared__ unsigned long long spi[64], spj[64];
    __shared__ float red[8];
    int tid = threadIdx.x;
    int warp = tid >> 5, lane = tid & 31;
    int wi = warp >> 2, wj = warp & 3;
    const __nv_bfloat16* Ag = g_znh + it * 64 * C_DIM;
    const __nv_bfloat16* Bg = g_znh + jt * 64 * C_DIM;
    if (tid < 64)       spi[tid] = g_pat[it * 64 + tid];
    else if (tid < 128) spj[tid - 64] = g_pat[jt * 64 + tid - 64];

    uint32_t sA = (uint32_t)__cvta_generic_to_shared(Ahs);
    uint32_t sB = (uint32_t)__cvta_generic_to_shared(Bhs);
    float acc[2][2][4] = {};

    for (int kc = 0; kc < C_DIM; kc += HM_KC) {
        __syncthreads();
        #pragma unroll
        for (int i = 0; i < 4; i++) {
            int g = tid + i * 256;
            int row = g >> 4, c8 = (g & 15) * 8;
            uint4 a = *(const uint4*)&Ag[row * C_DIM + kc + c8];
            *(uint4*)&Ahs[row * HM_LDS + c8] = a;
            uint4 b = *(const uint4*)&Bg[row * C_DIM + kc + c8];
            *(uint4*)&Bhs[row * HM_LDS + c8] = b;
        }
        __syncthreads();
        #pragma unroll
        for (int ks = 0; ks < HM_KC / 16; ks++) {
            int k0 = ks * 16;
            uint32_t a[2][4], b[2][2];
            #pragma unroll
            for (int mt = 0; mt < 2; mt++) {
                int rb = wi * 32 + mt * 16;
                uint32_t addr = sA + ((rb + (lane & 15)) * HM_LDS + k0 + (lane >> 4) * 8) * 2;
                ldsm_x4(a[mt][0], a[mt][1], a[mt][2], a[mt][3], addr);
            }
            #pragma unroll
            for (int nt = 0; nt < 2; nt++) {
                int nb = wj * 16 + nt * 8;
                uint32_t addr = sB + ((nb + (lane & 7)) * HM_LDS + k0 + ((lane >> 3) & 1) * 8) * 2;
                ldsm_x2(b[nt][0], b[nt][1], addr);
            }
            #pragma unroll
            for (int mt = 0; mt < 2; mt++)
                #pragma unroll
                for (int nt = 0; nt < 2; nt++)
                    mma_bf16(acc[mt][nt], a[mt][0], a[mt][1], a[mt][2], a[mt][3],
                             b[nt][0], b[nt][1]);
        }
    }

    float ws = 0.f, wc = 0.f;
    #pragma unroll
    for (int mt = 0; mt < 2; mt++) {
        #pragma unroll
        for (int nt = 0; nt < 2; nt++) {
            int li0 = wi * 32 + mt * 16 + (lane >> 2);
            int lj0 = wj * 16 + nt * 8 + (lane & 3) * 2;
            #pragma unroll
            for (int hh = 0; hh < 2; hh++) {
                int li = li0 + hh * 8;
                int gi = it * 64 + li;
                unsigned long long pi = spi[li];
                #pragma unroll
                for (int jj = 0; jj < 2; jj++) {
                    int lj = lj0 + jj;
                    int gj = jt * 64 + lj;
                    int h = __popcll(pi ^ spj[lj]);
                    if (gi != gj && h <= 5) {
                        float w = 1.0f - (float)h * (1.0f / 64.0f);
                        ws += w;
                        wc += w * acc[mt][nt][hh * 2 + jj];
                    }
                }
            }
        }
    }
    float scale = (it == jt) ? 1.0f : 2.0f;
    float wsb = bsum256(ws * scale, red);
    float wcb = bsum256(wc * scale, red);
    if (tid == 0) {
        atomicAdd(&g_sums[2], wsb);
        atomicAdd(&g_sums[3], wcb);
    }
}

// ---------------- K6: final scalar combine ----------------
__global__ __launch_bounds__(256) void k_final(float* __restrict__ out) {
    __shared__ float red[8];
    int t = threadIdx.x;
    float v = 0.f;
    #pragma unroll
    for (int q = 0; q < 4; q++) {
        float p = g_avgp[t + q * 256];
        v += p * logf(p + 1e-5f);
    }
    float s = bsum256(v, red);
    if (t == 0) {
        float sse  = g_sums[0];
        float sent = g_sums[1];
        float sw   = g_sums[2];
        float swc  = g_sums[3];
        float codebook_loss = sse / (float)(N_ROWS * C_DIM);
        float commit_loss   = 0.25f * codebook_loss;
        float sample_entropy = sent / (float)N_ROWS;
        float avg_entropy    = -s;
        float ent_loss = 0.1f * (sample_entropy - avg_entropy);
        float ham_loss = (sw - swc) / (sw + 1e-8f);
        out[OUT_LOSS] = codebook_loss + commit_loss + ent_loss + ham_loss;
    }
}

// ---------------- launch ----------------
extern "C" void kernel_launch(void* const* d_in, const int* in_sizes, int n_in,
                              void* d_out, int out_size) {
    const float* input_blocks = (const float*)d_in[0];
    const float* z_e          = (const float*)d_in[1];
    const float* codebook     = (const float*)d_in[2];
    float* out = (float*)d_out;

    k_zero<<<1, 1024>>>();
    k_norm_z<<<N_ROWS, 256>>>(z_e);
    k_norm_cb<<<K_CODES, 256>>>(codebook);
    k_pattern<<<N_ROWS / 4, 256>>>(input_blocks);
    k_affinity<<<dim3(K_CODES / TS, N_ROWS / TS), 256>>>();
    k_row<<<N_ROWS, 256>>>(out);
    k_ham<<<dim3(N_ROWS / 64, N_ROWS / 64), 256>>>();
    k_final<<<1, 256>>>(out);
}

// round 4
// speedup vs baseline: 2.3287x; 1.4233x over previous
#include <cuda_runtime.h>
#include <cuda_bf16.h>
#include <math.h>
#include <stdint.h>

#define N_ROWS 3456      // 16 * 216
#define C_DIM  256
#define K_CODES 1024
#define B_SZ   16
#define SPAT   216       // 6*6*6
#define VOX    13824     // 24^3
#define OUT_ZQ (B_SZ * C_DIM * SPAT)   // 884736
#define OUT_LOSS OUT_ZQ
#define OUT_IDX (OUT_ZQ + 1)

// ---------------- device scratch ----------------
__device__ float g_zn[N_ROWS * C_DIM];          // fp32 normalized z
__device__ float g_zhi[N_ROWS * C_DIM];         // tf32 hi part
__device__ float g_zlo[N_ROWS * C_DIM];         // tf32 lo part
__device__ __nv_bfloat16 g_znh[N_ROWS * C_DIM]; // bf16 copy (cos GEMM)
__device__ float g_en[K_CODES * C_DIM];         // fp32 normalized codebook
__device__ float g_ehi[K_CODES * C_DIM];
__device__ float g_elo[K_CODES * C_DIM];
__device__ float g_aff[N_ROWS * K_CODES];
__device__ unsigned long long g_pat[N_ROWS];
__device__ float g_avgp[K_CODES];
__device__ float g_sums[8];  // 0: SSE, 1: sample-entropy sum, 2: sumW, 3: sumWcos

// ---------------- helpers ----------------
__device__ __forceinline__ float bsum256(float v, float* red) {
    #pragma unroll
    for (int o = 16; o; o >>= 1) v += __shfl_xor_sync(0xffffffffu, v, o);
    __syncthreads();
    if ((threadIdx.x & 31) == 0) red[threadIdx.x >> 5] = v;
    __syncthreads();
    float s = 0.f;
    #pragma unroll
    for (int w = 0; w < 8; w++) s += red[w];
    return s;
}

__device__ __forceinline__ uint32_t f2tf32(float v) {
    uint32_t u;
    asm("cvt.rna.tf32.f32 %0, %1;" : "=r"(u) : "f"(v));
    return u;
}

__device__ __forceinline__ void ldsm_x4(uint32_t& r0, uint32_t& r1, uint32_t& r2, uint32_t& r3, uint32_t addr) {
    asm volatile("ldmatrix.sync.aligned.m8n8.x4.shared.b16 {%0,%1,%2,%3}, [%4];"
                 : "=r"(r0), "=r"(r1), "=r"(r2), "=r"(r3) : "r"(addr));
}
__device__ __forceinline__ void ldsm_x2(uint32_t& r0, uint32_t& r1, uint32_t addr) {
    asm volatile("ldmatrix.sync.aligned.m8n8.x2.shared.b16 {%0,%1}, [%2];"
                 : "=r"(r0), "=r"(r1) : "r"(addr));
}
__device__ __forceinline__ void mma_bf16(float* c, uint32_t a0, uint32_t a1, uint32_t a2, uint32_t a3,
                                         uint32_t b0, uint32_t b1) {
    asm volatile("mma.sync.aligned.m16n8k16.row.col.f32.bf16.bf16.f32 "
                 "{%0,%1,%2,%3}, {%4,%5,%6,%7}, {%8,%9}, {%0,%1,%2,%3};"
                 : "+f"(c[0]), "+f"(c[1]), "+f"(c[2]), "+f"(c[3])
                 : "r"(a0), "r"(a1), "r"(a2), "r"(a3), "r"(b0), "r"(b1));
}
__device__ __forceinline__ void mma_tf32(float* c, float a0, float a1, float a2, float a3,
                                         float b0, float b1) {
    asm volatile("mma.sync.aligned.m16n8k8.row.col.f32.tf32.tf32.f32 "
                 "{%0,%1,%2,%3}, {%4,%5,%6,%7}, {%8,%9}, {%0,%1,%2,%3};"
                 : "+f"(c[0]), "+f"(c[1]), "+f"(c[2]), "+f"(c[3])
                 : "r"(__float_as_uint(a0)), "r"(__float_as_uint(a1)),
                   "r"(__float_as_uint(a2)), "r"(__float_as_uint(a3)),
                   "r"(__float_as_uint(b0)), "r"(__float_as_uint(b1)));
}

// ---------------- K0: zero accumulators ----------------
__global__ void k_zero() {
    int t = threadIdx.x;
    if (t < K_CODES) g_avgp[t] = 0.f;
    if (t < 8) g_sums[t] = 0.f;
}

// ---------------- K1: normalize z rows (+ tf32 hi/lo + bf16) ----------------
__global__ void k_norm_z(const float* __restrict__ z_e) {
    int n = blockIdx.x, c = threadIdx.x;
    int b = n / SPAT, s = n % SPAT;
    __shared__ float red[8];
    float v = z_e[(b * C_DIM + c) * SPAT + s];
    float ss = bsum256(v * v, red);
    float nrm = sqrtf(ss);
    float vn = v / fmaxf(nrm, 1e-12f);
    g_zn[n * C_DIM + c] = vn;
    float hi = __uint_as_float(f2tf32(vn));
    g_zhi[n * C_DIM + c] = hi;
    g_zlo[n * C_DIM + c] = __uint_as_float(f2tf32(vn - hi));
    g_znh[n * C_DIM + c] = __float2bfloat16_rn(vn);
}

// ---------------- K2: normalize codebook rows (+ tf32 hi/lo) ----------------
__global__ void k_norm_cb(const float* __restrict__ cb) {
    int k = blockIdx.x, c = threadIdx.x;
    __shared__ float red[8];
    float v = cb[k * C_DIM + c];
    float ss = bsum256(v * v, red);
    float nrm = sqrtf(ss);
    float vn = v / fmaxf(nrm, 1e-12f);
    g_en[k * C_DIM + c] = vn;
    float hi = __uint_as_float(f2tf32(vn));
    g_ehi[k * C_DIM + c] = hi;
    g_elo[k * C_DIM + c] = __uint_as_float(f2tf32(vn - hi));
}

// ---------------- K3: patterns via float4 (4 voxels/thread) ----------------
__global__ __launch_bounds__(128) void k_pattern(const float* __restrict__ inp) {
    int t = threadIdx.x;
    int v0 = (blockIdx.x * 128 + t) * 4;   // first voxel of this thread
    int b = v0 / VOX, s = v0 % VOX;
    const float* p = inp + (size_t)b * 32 * VOX + s;
    float4 x = *(const float4*)&p[0];
    float best[4] = {x.x, x.y, x.z, x.w};
    int bi[4] = {0, 0, 0, 0};
    #pragma unroll
    for (int c = 1; c < 32; c++) {
        float4 y = *(const float4*)&p[c * VOX];
        if (y.x > best[0]) { best[0] = y.x; bi[0] = c; }
        if (y.y > best[1]) { best[1] = y.y; bi[1] = c; }
        if (y.z > best[2]) { best[2] = y.z; bi[2] = c; }
        if (y.w > best[3]) { best[3] = y.w; bi[3] = c; }
    }
    unsigned nib = (bi[0] != 0) | ((bi[1] != 0) << 1) | ((bi[2] != 0) << 2) | ((bi[3] != 0) << 3);
    __shared__ unsigned char snib[128];
    snib[t] = (unsigned char)nib;
    __syncthreads();
    if (t < 8) {   // 8 patterns per block (128 thr * 4 vox = 512 vox)
        unsigned long long pat = 0;
        #pragma unroll
        for (int i = 0; i < 16; i++)
            pat |= (unsigned long long)snib[t * 16 + i] << (i * 4);
        g_pat[blockIdx.x * 8 + t] = pat;
    }
}

// ---------------- K4a: affinity via 3xTF32 mma ----------------
// 64x64 tile, 8 warps 2x4, warp tile 32x16, m16n8k8, KC=32
#define A3_KC 32
#define A3_LDS 36
__global__ __launch_bounds__(256) void k_affinity() {
    __shared__ float Ah[64 * A3_LDS], Al[64 * A3_LDS];
    __shared__ float Bh[64 * A3_LDS], Bl[64 * A3_LDS];
    int tid = threadIdx.x;
    int warp = tid >> 5, lane = tid & 31;
    int wi = warp >> 2, wj = warp & 3;
    int rowBase = blockIdx.y * 64;
    int colBase = blockIdx.x * 64;
    const float* Azh = g_zhi + rowBase * C_DIM;
    const float* Azl = g_zlo + rowBase * C_DIM;
    const float* Beh = g_ehi + colBase * C_DIM;
    const float* Bel = g_elo + colBase * C_DIM;
    float acc[2][2][4] = {};
    int r = lane >> 2, cq = lane & 3;

    for (int kc = 0; kc < C_DIM; kc += A3_KC) {
        __syncthreads();
        #pragma unroll
        for (int i = 0; i < 2; i++) {
            int g = tid + i * 256;
            int row = g >> 3, c4 = (g & 7) * 4;
            *(float4*)&Ah[row * A3_LDS + c4] = *(const float4*)&Azh[row * C_DIM + kc + c4];
            *(float4*)&Al[row * A3_LDS + c4] = *(const float4*)&Azl[row * C_DIM + kc + c4];
            *(float4*)&Bh[row * A3_LDS + c4] = *(const float4*)&Beh[row * C_DIM + kc + c4];
            *(float4*)&Bl[row * A3_LDS + c4] = *(const float4*)&Bel[row * C_DIM + kc + c4];
        }
        __syncthreads();
        #pragma unroll
        for (int ks = 0; ks < A3_KC / 8; ks++) {
            int k0 = ks * 8;
            float ah[2][4], al[2][4], bh[2][2], bl[2][2];
            #pragma unroll
            for (int mt = 0; mt < 2; mt++) {
                int rb = wi * 32 + mt * 16;
                ah[mt][0] = Ah[(rb + r) * A3_LDS + k0 + cq];
                ah[mt][1] = Ah[(rb + r + 8) * A3_LDS + k0 + cq];
                ah[mt][2] = Ah[(rb + r) * A3_LDS + k0 + cq + 4];
                ah[mt][3] = Ah[(rb + r + 8) * A3_LDS + k0 + cq + 4];
                al[mt][0] = Al[(rb + r) * A3_LDS + k0 + cq];
                al[mt][1] = Al[(rb + r + 8) * A3_LDS + k0 + cq];
                al[mt][2] = Al[(rb + r) * A3_LDS + k0 + cq + 4];
                al[mt][3] = Al[(rb + r + 8) * A3_LDS + k0 + cq + 4];
            }
            #pragma unroll
            for (int nt = 0; nt < 2; nt++) {
                int nb = wj * 16 + nt * 8;
                bh[nt][0] = Bh[(nb + r) * A3_LDS + k0 + cq];
                bh[nt][1] = Bh[(nb + r) * A3_LDS + k0 + cq + 4];
                bl[nt][0] = Bl[(nb + r) * A3_LDS + k0 + cq];
                bl[nt][1] = Bl[(nb + r) * A3_LDS + k0 + cq + 4];
            }
            #pragma unroll
            for (int mt = 0; mt < 2; mt++)
                #pragma unroll
                for (int nt = 0; nt < 2; nt++) {
                    mma_tf32(acc[mt][nt], ah[mt][0], ah[mt][1], ah[mt][2], ah[mt][3],
                             bh[nt][0], bh[nt][1]);
                    mma_tf32(acc[mt][nt], ah[mt][0], ah[mt][1], ah[mt][2], ah[mt][3],
                             bl[nt][0], bl[nt][1]);
                    mma_tf32(acc[mt][nt], al[mt][0], al[mt][1], al[mt][2], al[mt][3],
                             bh[nt][0], bh[nt][1]);
                }
        }
    }
    #pragma unroll
    for (int mt = 0; mt < 2; mt++) {
        #pragma unroll
        for (int nt = 0; nt < 2; nt++) {
            int i0 = rowBase + wi * 32 + mt * 16 + (lane >> 2);
            int j0 = colBase + wj * 16 + nt * 8 + (lane & 3) * 2;
            *(float2*)&g_aff[i0 * K_CODES + j0] = make_float2(acc[mt][nt][0], acc[mt][nt][1]);
            *(float2*)&g_aff[(i0 + 8) * K_CODES + j0] = make_float2(acc[mt][nt][2], acc[mt][nt][3]);
        }
    }
}

// ---------------- K4b: per-row pass, 8 rows per block ----------------
#define ROWS_PB 8
__global__ __launch_bounds__(256) void k_row(float* __restrict__ out) {
    int n0 = blockIdx.x * ROWS_PB, t = threadIdx.x;
    __shared__ float redA[8], redB[8], redC[8];
    __shared__ float redm[8];
    __shared__ int   redi[8];

    float avg_acc[4] = {0.f, 0.f, 0.f, 0.f};
    float ent_acc = 0.f, sse_acc = 0.f;

    for (int rr = 0; rr < ROWS_PB; rr++) {
        int n = n0 + rr;
        float fa[4];
        #pragma unroll
        for (int q = 0; q < 4; q++)
            fa[q] = g_aff[n * K_CODES + t + q * 256] * 100.0f;

        // block argmax
        float m = fa[0]; int mi = t;
        #pragma unroll
        for (int q = 1; q < 4; q++)
            if (fa[q] > m) { m = fa[q]; mi = t + q * 256; }
        #pragma unroll
        for (int o = 16; o; o >>= 1) {
            float om = __shfl_xor_sync(0xffffffffu, m, o);
            int   oi = __shfl_xor_sync(0xffffffffu, mi, o);
            if (om > m || (om == m && oi < mi)) { m = om; mi = oi; }
        }
        if ((t & 31) == 0) { redm[t >> 5] = m; redi[t >> 5] = mi; }
        __syncthreads();
        float bm = redm[0]; int bidx = redi[0];
        #pragma unroll
        for (int w = 1; w < 8; w++)
            if (redm[w] > bm || (redm[w] == bm && redi[w] < bidx)) { bm = redm[w]; bidx = redi[w]; }

        // softmax pieces + SSE, one fused 3-way reduction
        float e[4], se = 0.f, te = 0.f;
        #pragma unroll
        for (int q = 0; q < 4; q++) {
            float d = fa[q] - bm;
            e[q] = expf(d);
            se += e[q];
            te += e[q] * d;
        }
        float zq = g_en[bidx * C_DIM + t];
        float zn = g_zn[n * C_DIM + t];
        float dd = zq - zn;
        float sq = dd * dd;
        float v0 = se, v1 = te, v2 = sq;
        #pragma unroll
        for (int o = 16; o; o >>= 1) {
            v0 += __shfl_xor_sync(0xffffffffu, v0, o);
            v1 += __shfl_xor_sync(0xffffffffu, v1, o);
            v2 += __shfl_xor_sync(0xffffffffu, v2, o);
        }
        __syncthreads();
        if ((t & 31) == 0) { redA[t >> 5] = v0; redB[t >> 5] = v1; redC[t >> 5] = v2; }
        __syncthreads();
        float Z = 0.f, T = 0.f, S = 0.f;
        #pragma unroll
        for (int w = 0; w < 8; w++) { Z += redA[w]; T += redB[w]; S += redC[w]; }

        if (t == 0) {
            ent_acc += logf(Z) - T / Z;
            sse_acc += S;
            out[OUT_IDX + n] = (float)bidx;
        }
        float invZ = 1.0f / Z;
        #pragma unroll
        for (int q = 0; q < 4; q++) avg_acc[q] += e[q] * invZ;

        int b = n / SPAT, s = n % SPAT;
        out[(b * C_DIM + t) * SPAT + s] = zq;
        __syncthreads();   // protect redm/redi for next row
    }

    const float invN = 1.0f / (float)N_ROWS;
    #pragma unroll
    for (int q = 0; q < 4; q++)
        atomicAdd(&g_avgp[t + q * 256], avg_acc[q] * invN);
    if (t == 0) {
        atomicAdd(&g_sums[1], ent_acc);
        atomicAdd(&g_sums[0], sse_acc);
    }
}

// ---------------- K5: fused cos GEMM (bf16 mma) + hamming reduce ----------------
#define HM_KC 128
#define HM_LDS 136
__global__ __launch_bounds__(256) void k_ham() {
    int it = blockIdx.y, jt = blockIdx.x;
    if (jt < it) return;
    __shared__ __nv_bfloat16 Ahs[64 * HM_LDS];
    __shared__ __nv_bfloat16 Bhs[64 * HM_LDS];
    __shared__ unsigned long long spi[64], spj[64];
    __shared__ float red[8];
    int tid = threadIdx.x;
    int warp = tid >> 5, lane = tid & 31;
    int wi = warp >> 2, wj = warp & 3;
    const __nv_bfloat16* Ag = g_znh + it * 64 * C_DIM;
    const __nv_bfloat16* Bg = g_znh + jt * 64 * C_DIM;
    if (tid < 64)       spi[tid] = g_pat[it * 64 + tid];
    else if (tid < 128) spj[tid - 64] = g_pat[jt * 64 + tid - 64];

    uint32_t sA = (uint32_t)__cvta_generic_to_shared(Ahs);
    uint32_t sB = (uint32_t)__cvta_generic_to_shared(Bhs);
    float acc[2][2][4] = {};

    for (int kc = 0; kc < C_DIM; kc += HM_KC) {
        __syncthreads();
        #pragma unroll
        for (int i = 0; i < 4; i++) {
            int g = tid + i * 256;
            int row = g >> 4, c8 = (g & 15) * 8;
            *(uint4*)&Ahs[row * HM_LDS + c8] = *(const uint4*)&Ag[row * C_DIM + kc + c8];
            *(uint4*)&Bhs[row * HM_LDS + c8] = *(const uint4*)&Bg[row * C_DIM + kc + c8];
        }
        __syncthreads();
        #pragma unroll
        for (int ks = 0; ks < HM_KC / 16; ks++) {
            int k0 = ks * 16;
            uint32_t a[2][4], b[2][2];
            #pragma unroll
            for (int mt = 0; mt < 2; mt++) {
                int rb = wi * 32 + mt * 16;
                uint32_t addr = sA + ((rb + (lane & 15)) * HM_LDS + k0 + (lane >> 4) * 8) * 2;
                ldsm_x4(a[mt][0], a[mt][1], a[mt][2], a[mt][3], addr);
            }
            #pragma unroll
            for (int nt = 0; nt < 2; nt++) {
                int nb = wj * 16 + nt * 8;
                uint32_t addr = sB + ((nb + (lane & 7)) * HM_LDS + k0 + ((lane >> 3) & 1) * 8) * 2;
                ldsm_x2(b[nt][0], b[nt][1], addr);
            }
            #pragma unroll
            for (int mt = 0; mt < 2; mt++)
                #pragma unroll
                for (int nt = 0; nt < 2; nt++)
                    mma_bf16(acc[mt][nt], a[mt][0], a[mt][1], a[mt][2], a[mt][3],
                             b[nt][0], b[nt][1]);
        }
    }

    float ws = 0.f, wc = 0.f;
    #pragma unroll
    for (int mt = 0; mt < 2; mt++) {
        #pragma unroll
        for (int nt = 0; nt < 2; nt++) {
            int li0 = wi * 32 + mt * 16 + (lane >> 2);
            int lj0 = wj * 16 + nt * 8 + (lane & 3) * 2;
            #pragma unroll
            for (int hh = 0; hh < 2; hh++) {
                int li = li0 + hh * 8;
                int gi = it * 64 + li;
                unsigned long long pi = spi[li];
                #pragma unroll
                for (int jj = 0; jj < 2; jj++) {
                    int lj = lj0 + jj;
                    int gj = jt * 64 + lj;
                    int h = __popcll(pi ^ spj[lj]);
                    if (gi != gj && h <= 5) {
                        float w = 1.0f - (float)h * (1.0f / 64.0f);
                        ws += w;
                        wc += w * acc[mt][nt][hh * 2 + jj];
                    }
                }
            }
        }
    }
    float scale = (it == jt) ? 1.0f : 2.0f;
    float wsb = bsum256(ws * scale, red);
    float wcb = bsum256(wc * scale, red);
    if (tid == 0) {
        atomicAdd(&g_sums[2], wsb);
        atomicAdd(&g_sums[3], wcb);
    }
}

// ---------------- K6: final scalar combine ----------------
__global__ __launch_bounds__(256) void k_final(float* __restrict__ out) {
    __shared__ float red[8];
    int t = threadIdx.x;
    float v = 0.f;
    #pragma unroll
    for (int q = 0; q < 4; q++) {
        float p = g_avgp[t + q * 256];
        v += p * logf(p + 1e-5f);
    }
    float s = bsum256(v, red);
    if (t == 0) {
        float sse  = g_sums[0];
        float sent = g_sums[1];
        float sw   = g_sums[2];
        float swc  = g_sums[3];
        float codebook_loss = sse / (float)(N_ROWS * C_DIM);
        float commit_loss   = 0.25f * codebook_loss;
        float sample_entropy = sent / (float)N_ROWS;
        float avg_entropy    = -s;
        float ent_loss = 0.1f * (sample_entropy - avg_entropy);
        float ham_loss = (sw - swc) / (sw + 1e-8f);
        out[OUT_LOSS] = codebook_loss + commit_loss + ent_loss + ham_loss;
    }
}

// ---------------- launch ----------------
extern "C" void kernel_launch(void* const* d_in, const int* in_sizes, int n_in,
                              void* d_out, int out_size) {
    const float* input_blocks = (const float*)d_in[0];
    const float* z_e          = (const float*)d_in[1];
    const float* codebook     = (const float*)d_in[2];
    float* out = (float*)d_out;

    k_zero<<<1, 1024>>>();
    k_norm_z<<<N_ROWS, 256>>>(z_e);
    k_norm_cb<<<K_CODES, 256>>>(codebook);
    k_pattern<<<(B_SZ * VOX) / 512, 128>>>(input_blocks);
    k_affinity<<<dim3(K_CODES / 64, N_ROWS / 64), 256>>>();
    k_row<<<N_ROWS / ROWS_PB, 256>>>(out);
    k_ham<<<dim3(N_ROWS / 64, N_ROWS / 64), 256>>>();
    k_final<<<1, 256>>>(out);
}